// round 16
// baseline (speedup 1.0000x reference)
#include <cuda_runtime.h>
#include <stdint.h>

#define GRID_N 256

// dx = fp32(20/255); R = fp32(1/dx). XLA rewrites A/dx -> A*(1/dx), constant-folded.
#define DXF (20.0f / 255.0f)
#define RF  (1.0f / DXF)

__device__ __forceinline__ uint64_t make_evict_last_policy()
{
    uint64_t p;
    asm("createpolicy.fractional.L2::evict_last.b64 %0, 1.0;" : "=l"(p));
    return p;
}

__device__ __forceinline__ void red_add_evict_last(float* addr, float v, uint64_t policy)
{
    asm volatile("red.global.add.L2::cache_hint.f32 [%0], %1, %2;"
                 :: "l"(addr), "f"(v), "l"(policy) : "memory");
}

__device__ __forceinline__ void st_zero4_evict_last(float4* addr, uint64_t policy)
{
    asm volatile("st.global.L2::cache_hint.v4.f32 [%0], {%1, %1, %1, %1}, %2;"
                 :: "l"(addr), "f"(0.0f), "l"(policy) : "memory");
}

// Zero the grid with evict_last priority. Maximally wide: ONE float4 store per
// thread, no loop — full CTA breadth finishes the LTS-capped store stream fast.
__global__ void __launch_bounds__(256) zero_grid_kernel_wide(float* __restrict__ grid, int n4)
{
    int t = blockIdx.x * blockDim.x + threadIdx.x;
    if (t < n4) {
        uint64_t policy = make_evict_last_policy();
        st_zero4_evict_last(&((float4*)grid)[t], policy);
    }
}

__device__ __forceinline__ void deposit(float px, float py, float pz, float w,
                                        float* __restrict__ grid, uint64_t policy)
{
    // fi = (p + 10) * R ; then fi + 0.5, trunc toward zero.
    // __fmul_rn/__fadd_rn forbid FFMA contraction (XLA emits separate mul/add).
    float fx = __fadd_rn(__fmul_rn(__fadd_rn(px, 10.0f), RF), 0.5f);
    float fy = __fadd_rn(__fmul_rn(__fadd_rn(py, 10.0f), RF), 0.5f);
    float fz = __fadd_rn(__fmul_rn(__fadd_rn(pz, 10.0f), RF), 0.5f);

    int ix = (int)fx;   // cvt.rzi: trunc toward zero == astype(int32)
    int iy = (int)fy;
    int iz = (int)fz;

    bool in_grid = (ix >= 0) & (ix < GRID_N) &
                   (iy >= 0) & (iy < GRID_N) &
                   (iz >= 0) & (iz < GRID_N);
    if (in_grid) {
        int flat = (ix * GRID_N + iy) * GRID_N + iz;
        red_add_evict_last(&grid[flat], w, policy);
    }
}

// R14 body, persistent launch: exact same 4-particle deposit sequence, wrapped
// in a grid-stride loop over groups. Only delta vs R14 = launch shape (kills
// the 0.25-wave tail); only delta vs R13 = no software pipeline.
__global__ void __launch_bounds__(256, 8) scatter_kernel_v4_persist(
    const float* __restrict__ positions,  // [N,3]
    const float* __restrict__ weights,    // [N]
    float* __restrict__ grid,
    int n_groups,
    int n_particles)
{
    const float4* p4 = (const float4*)positions;
    const float4* w4 = (const float4*)weights;
    uint64_t policy = make_evict_last_policy();

    int stride = gridDim.x * blockDim.x;
    int t = blockIdx.x * blockDim.x + threadIdx.x;

    for (int g = t; g < n_groups; g += stride) {
        float4 a = __ldcs(&p4[3 * g + 0]);
        float4 b = __ldcs(&p4[3 * g + 1]);
        float4 c = __ldcs(&p4[3 * g + 2]);
        float4 w = __ldcs(&w4[g]);

        deposit(a.x, a.y, a.z, w.x, grid, policy);
        deposit(a.w, b.x, b.y, w.y, grid, policy);
        deposit(b.z, b.w, c.x, w.z, grid, policy);
        deposit(c.y, c.z, c.w, w.w, grid, policy);
    }

    // Tail particles (n_particles % 4)
    int tail_start = n_groups * 4;
    for (int i = tail_start + t; i < n_particles; i += stride) {
        float px = __ldcs(&positions[3 * i + 0]);
        float py = __ldcs(&positions[3 * i + 1]);
        float pz = __ldcs(&positions[3 * i + 2]);
        float w  = __ldcs(&weights[i]);
        deposit(px, py, pz, w, grid, policy);
    }
}

extern "C" void kernel_launch(void* const* d_in, const int* in_sizes, int n_in,
                              void* d_out, int out_size)
{
    const float* positions = (const float*)d_in[0];
    const float* weights   = (const float*)d_in[1];
    float* grid            = (float*)d_out;

    int n_particles = in_sizes[1];  // weights has N elements; positions has 3N
    int n_groups = n_particles / 4;

    // Zero + park grid in L2 with evict_last priority (maximally wide launch).
    {
        int n4 = out_size / 4;
        int threads = 256;
        int blocks = (n4 + threads - 1) / threads;
        zero_grid_kernel_wide<<<blocks, threads>>>(grid, n4);
    }

    // One full wave: 148 SMs x 8 CTAs x 256 threads.
    int threads = 256;
    int blocks = 148 * 8;
    scatter_kernel_v4_persist<<<blocks, threads>>>(positions, weights, grid,
                                                   n_groups, n_particles);
}